// round 6
// baseline (speedup 1.0000x reference)
#include <cuda_runtime.h>

// Problem constants
#define N_TOK  262144
#define K_CB   1024
#define D_EMB  64
#define DECAY  0.99f
#define EPSV   1e-5f
#define COMMIT 0.25f

// Output layout (float32 blob, reference return order)
#define OFF_Q    0
#define OFF_LOSS 16777216
#define OFF_IDX  16777217
#define OFF_CB   17039361   // odd -> only 4-byte aligned
#define OFF_CS   17104897
#define OFF_EW   17105921   // odd -> only 4-byte aligned

// Scratch (device globals; no allocations allowed)
__device__ float g_dw[K_CB * D_EMB];
__device__ float g_counts[K_CB];
__device__ float g_loss;
__device__ float g_cnorm[K_CB];
__device__ float g_n;

typedef unsigned long long u64;

// ---- packed f32x2 helpers (per-lane IEEE rounding == scalar FFMA) ----------
__device__ __forceinline__ void ffma2(u64& d, u64 a, u64 b) {
    asm("fma.rn.f32x2 %0, %1, %2, %0;" : "+l"(d) : "l"(a), "l"(b));
}
__device__ __forceinline__ float2 unpack2(u64 v) {
    float2 r; asm("mov.b64 {%0, %1}, %2;" : "=f"(r.x), "=f"(r.y) : "l"(v)); return r;
}

// ---------------------------------------------------------------------------
// Zero scratch (graph replays require determinism)
// ---------------------------------------------------------------------------
__global__ void vq_zero_kernel() {
    int i = blockIdx.x * blockDim.x + threadIdx.x;
    if (i < K_CB * D_EMB) g_dw[i] = 0.0f;
    if (i < K_CB)         g_counts[i] = 0.0f;
    if (i == 0)           g_loss = 0.0f;
}

// ---------------------------------------------------------------------------
// Precompute ||c||^2 per code (identical arithmetic to R2)
// ---------------------------------------------------------------------------
__global__ void vq_cnorm_kernel(const float* __restrict__ codebook) {
    int k = blockIdx.x * blockDim.x + threadIdx.x;
    if (k >= K_CB) return;
    const float4* c = reinterpret_cast<const float4*>(codebook + k * D_EMB);
    float s0 = 0.f, s1 = 0.f, s2 = 0.f, s3 = 0.f;
#pragma unroll
    for (int i = 0; i < D_EMB / 4; i++) {
        float4 v = c[i];
        s0 += v.x * v.x; s1 += v.y * v.y;
        s2 += v.z * v.z; s3 += v.w * v.w;
    }
    g_cnorm[k] = (s0 + s1) + (s2 + s3);
}

// ---------------------------------------------------------------------------
// Main fused kernel, 4 tokens per thread. Each token's accumulation chains
// are bit-identical to the validated R2/R4/R5 ordering (ZERO argmin flips on
// this fixed dataset is a hard requirement):
//   lane-x of aXY == s0 chain, lane-y == s1; aZW -> (s2,s3);
//   dot = (s0+s1)+(s2+s3); d = cn - 2.0f*dot; strict-< first-min.
// 16 broadcast LDS.128 per code feed 128 FFMA2 (4 tokens): LDS pipe load
// per token halves again vs R5.
// ---------------------------------------------------------------------------
#define TPB   128
#define CHUNK 128
#define TOKS  4

__global__ void __launch_bounds__(TPB, 2)
vq_assign_kernel(const float* __restrict__ inputs,
                 const float* __restrict__ codebook,
                 float* __restrict__ out) {
    __shared__ float s_c[CHUNK * D_EMB];   // 32 KB code chunk
    __shared__ float s_cn[CHUNK];
    __shared__ float s_counts[K_CB];       // 4 KB per-block count aggregation
    __shared__ float s_red[TPB / 32];

    const int tid = threadIdx.x;
    const int gid0 = blockIdx.x * (TOKS * TPB) + tid;  // tokens: gid0 + t*TPB

    for (int i = tid; i < K_CB; i += TPB) s_counts[i] = 0.0f;

    // load 4 input vectors as packed f32x2 pairs
    ulonglong2 xs[TOKS][16];
#pragma unroll
    for (int t = 0; t < TOKS; t++) {
        const ulonglong2* xp =
            reinterpret_cast<const ulonglong2*>(inputs + (size_t)(gid0 + t * TPB) * D_EMB);
#pragma unroll
        for (int i = 0; i < 16; i++) xs[t][i] = xp[i];
    }

    float best[TOKS];
    int   bidx[TOKS];
#pragma unroll
    for (int t = 0; t < TOKS; t++) { best[t] = 3.4028235e38f; bidx[t] = 0; }

    for (int ch = 0; ch < K_CB / CHUNK; ch++) {
        __syncthreads();
        const float4* cp = reinterpret_cast<const float4*>(codebook + (size_t)ch * CHUNK * D_EMB);
        float4* scp = reinterpret_cast<float4*>(s_c);
#pragma unroll
        for (int i = 0; i < (CHUNK * D_EMB / 4) / TPB; i++)
            scp[tid + i * TPB] = cp[tid + i * TPB];
        if (tid < CHUNK) s_cn[tid] = g_cnorm[ch * CHUNK + tid];
        __syncthreads();

        for (int j = 0; j < CHUNK; j++) {
            const ulonglong2* csh = reinterpret_cast<const ulonglong2*>(s_c + j * D_EMB);
            u64 aXY[TOKS], aZW[TOKS];
#pragma unroll
            for (int t = 0; t < TOKS; t++) { aXY[t] = 0; aZW[t] = 0; }
#pragma unroll
            for (int i = 0; i < 16; i++) {
                ulonglong2 c2 = csh[i];   // LDS.128 broadcast, shared by 4 tokens
#pragma unroll
                for (int t = 0; t < TOKS; t++) {
                    ffma2(aXY[t], xs[t][i].x, c2.x);
                    ffma2(aZW[t], xs[t][i].y, c2.y);
                }
            }
            float cn = s_cn[j];
#pragma unroll
            for (int t = 0; t < TOKS; t++) {
                float2 uxy = unpack2(aXY[t]);
                float2 uzw = unpack2(aZW[t]);
                float dot = (uxy.x + uxy.y) + (uzw.x + uzw.y);
                float d = cn - 2.0f * dot;
                if (d < best[t]) { best[t] = d; bidx[t] = ch * CHUNK + j; }
            }
        }
    }

    // per-block count aggregation
#pragma unroll
    for (int t = 0; t < TOKS; t++) atomicAdd(&s_counts[bidx[t]], 1.0f);

    // gather + quantized store + loss + dw for all tokens
    float lsum = 0.0f;
#pragma unroll
    for (int t = 0; t < TOKS; t++) {
        const int gid = gid0 + t * TPB;
        const int bi = bidx[t];
        const float4* cch = reinterpret_cast<const float4*>(codebook + (size_t)bi * D_EMB);
        float4* qout = reinterpret_cast<float4*>(out + OFF_Q + (size_t)gid * D_EMB);
        float* dwrow = g_dw + (size_t)bi * D_EMB;
#pragma unroll
        for (int i = 0; i < 16; i++) {
            float4 c4 = cch[i];
            qout[i] = c4;
            float2 lo = unpack2(xs[t][i].x);
            float2 hi = unpack2(xs[t][i].y);
            float dx = c4.x - lo.x, dy = c4.y - lo.y;
            float dz = c4.z - hi.x, dwv = c4.w - hi.y;
            lsum += dx * dx + dy * dy + dz * dz + dwv * dwv;
            atomicAdd(dwrow + 4 * i + 0, lo.x);
            atomicAdd(dwrow + 4 * i + 1, lo.y);
            atomicAdd(dwrow + 4 * i + 2, hi.x);
            atomicAdd(dwrow + 4 * i + 3, hi.y);
        }
        out[OFF_IDX + gid] = (float)bi;
    }

    // block-reduce loss partial -> one global atomic per block
#pragma unroll
    for (int o = 16; o > 0; o >>= 1)
        lsum += __shfl_xor_sync(0xFFFFFFFFu, lsum, o);
    if ((tid & 31) == 0) s_red[tid >> 5] = lsum;
    __syncthreads();
    if (tid == 0) {
        float tt = 0.f;
#pragma unroll
        for (int w = 0; w < TPB / 32; w++) tt += s_red[w];
        atomicAdd(&g_loss, tt);
    }

    // flush block-local counts
    for (int i = tid; i < K_CB; i += TPB) {
        float v = s_counts[i];
        if (v != 0.0f) atomicAdd(&g_counts[i], v);
    }
}

// ---------------------------------------------------------------------------
// Stage 1 of finalize: new_cluster_size, n-reduction, loss. One block.
// ---------------------------------------------------------------------------
__global__ void __launch_bounds__(K_CB)
vq_ncs_kernel(const float* __restrict__ ema_cs, float* __restrict__ out) {
    __shared__ float s_n[K_CB];
    const int k = threadIdx.x;

    float ncs = DECAY * ema_cs[k] + (1.0f - DECAY) * g_counts[k];
    out[OFF_CS + k] = ncs;

    s_n[k] = ncs;
    __syncthreads();
#pragma unroll
    for (int s = K_CB / 2; s > 0; s >>= 1) {
        if (k < s) s_n[k] += s_n[k + s];
        __syncthreads();
    }
    if (k == 0) {
        g_n = s_n[0];
        out[OFF_LOSS] = COMMIT * g_loss / (float)((size_t)N_TOK * D_EMB);
    }
}

// ---------------------------------------------------------------------------
// Stage 2 of finalize: element-parallel EMA weight + codebook update.
// ---------------------------------------------------------------------------
__global__ void __launch_bounds__(256)
vq_update_kernel(const float* __restrict__ ema_w, float* __restrict__ out) {
    const int idx = blockIdx.x * 256 + threadIdx.x;   // 0 .. K*D-1
    const int k = idx >> 6;

    float ncs = out[OFF_CS + k];
    float n = g_n;
    float smoothed = (ncs + EPSV) / (n + (float)K_CB * EPSV) * n;

    float w = DECAY * ema_w[idx] + (1.0f - DECAY) * g_dw[idx];
    out[OFF_EW + idx] = w;
    out[OFF_CB + idx] = w / smoothed;
}

// ---------------------------------------------------------------------------
extern "C" void kernel_launch(void* const* d_in, const int* in_sizes, int n_in,
                              void* d_out, int out_size) {
    const float* inputs   = (const float*)d_in[0];
    const float* codebook = (const float*)d_in[1];
    const float* ema_cs   = (const float*)d_in[2];
    const float* ema_w    = (const float*)d_in[3];
    float* out = (float*)d_out;

    vq_zero_kernel<<<(K_CB * D_EMB + 255) / 256, 256>>>();
    vq_cnorm_kernel<<<(K_CB + 255) / 256, 256>>>(codebook);
    vq_assign_kernel<<<N_TOK / (TOKS * TPB), TPB>>>(inputs, codebook, out);
    vq_ncs_kernel<<<1, K_CB>>>(ema_cs, out);
    vq_update_kernel<<<(K_CB * D_EMB) / 256, 256>>>(ema_w, out);
}

// round 7
// speedup vs baseline: 1.5884x; 1.5884x over previous
#include <cuda_runtime.h>

// Problem constants
#define N_TOK  262144
#define K_CB   1024
#define D_EMB  64
#define DECAY  0.99f
#define EPSV   1e-5f
#define COMMIT 0.25f

// Output layout (float32 blob, reference return order)
#define OFF_Q    0
#define OFF_LOSS 16777216
#define OFF_IDX  16777217
#define OFF_CB   17039361   // odd -> only 4-byte aligned
#define OFF_CS   17104897
#define OFF_EW   17105921   // odd -> only 4-byte aligned

// Scratch (device globals; no allocations allowed)
__device__ float g_dw[K_CB * D_EMB];
__device__ float g_counts[K_CB];
__device__ float g_loss;
__device__ float g_cnorm[K_CB];
__device__ float g_n;

typedef unsigned long long u64;

// ---- packed f32x2 helpers (per-lane IEEE rounding == scalar FFMA) ----------
__device__ __forceinline__ void ffma2(u64& d, u64 a, u64 b) {
    asm("fma.rn.f32x2 %0, %1, %2, %0;" : "+l"(d) : "l"(a), "l"(b));
}
__device__ __forceinline__ float2 unpack2(u64 v) {
    float2 r; asm("mov.b64 {%0, %1}, %2;" : "=f"(r.x), "=f"(r.y) : "l"(v)); return r;
}

// ---------------------------------------------------------------------------
// Zero scratch (graph replays require determinism)
// ---------------------------------------------------------------------------
__global__ void vq_zero_kernel() {
    int i = blockIdx.x * blockDim.x + threadIdx.x;
    if (i < K_CB * D_EMB) g_dw[i] = 0.0f;
    if (i < K_CB)         g_counts[i] = 0.0f;
    if (i == 0)           g_loss = 0.0f;
}

// ---------------------------------------------------------------------------
// Precompute ||c||^2 per code (identical arithmetic to R2)
// ---------------------------------------------------------------------------
__global__ void vq_cnorm_kernel(const float* __restrict__ codebook) {
    int k = blockIdx.x * blockDim.x + threadIdx.x;
    if (k >= K_CB) return;
    const float4* c = reinterpret_cast<const float4*>(codebook + k * D_EMB);
    float s0 = 0.f, s1 = 0.f, s2 = 0.f, s3 = 0.f;
#pragma unroll
    for (int i = 0; i < D_EMB / 4; i++) {
        float4 v = c[i];
        s0 += v.x * v.x; s1 += v.y * v.y;
        s2 += v.z * v.z; s3 += v.w * v.w;
    }
    g_cnorm[k] = (s0 + s1) + (s2 + s3);
}

// ---------------------------------------------------------------------------
// Main fused kernel, 3 tokens per thread (192 x-regs + ~40 misc < 256-reg
// ceiling at 2 CTAs/SM; TOKS=4 spilled in R6 and regressed).
// Each token's accumulation chains are bit-identical to the validated
// R2/R4/R5 ordering (ZERO argmin flips is a hard requirement):
//   lane-x of aXY == s0 chain, lane-y == s1; aZW -> (s2,s3);
//   dot = (s0+s1)+(s2+s3); d = cn - 2.0f*dot; strict-< first-min.
// 16 broadcast LDS.128 per code feed 96 FFMA2 (3 tokens).
// N_TOK not divisible by 3*TPB -> uniform per-(block,t) validity guards;
// tail block computes on zeroed regs and skips loads/stores for slot t=2.
// ---------------------------------------------------------------------------
#define TPB   128
#define CHUNK 128
#define TOKS  3

__global__ void __launch_bounds__(TPB, 2)
vq_assign_kernel(const float* __restrict__ inputs,
                 const float* __restrict__ codebook,
                 float* __restrict__ out) {
    __shared__ float s_c[CHUNK * D_EMB];   // 32 KB code chunk
    __shared__ float s_cn[CHUNK];
    __shared__ float s_counts[K_CB];       // 4 KB per-block count aggregation
    __shared__ float s_red[TPB / 32];

    const int tid = threadIdx.x;
    const int gid0 = blockIdx.x * (TOKS * TPB) + tid;  // tokens: gid0 + t*TPB

    for (int i = tid; i < K_CB; i += TPB) s_counts[i] = 0.0f;

    // load up to 3 input vectors as packed f32x2 pairs (uniform guards)
    ulonglong2 xs[TOKS][16];
#pragma unroll
    for (int t = 0; t < TOKS; t++) {
        if (gid0 + t * TPB < N_TOK) {
            const ulonglong2* xp =
                reinterpret_cast<const ulonglong2*>(inputs + (size_t)(gid0 + t * TPB) * D_EMB);
#pragma unroll
            for (int i = 0; i < 16; i++) xs[t][i] = xp[i];
        } else {
#pragma unroll
            for (int i = 0; i < 16; i++) { xs[t][i].x = 0ULL; xs[t][i].y = 0ULL; }
        }
    }

    float best[TOKS];
    int   bidx[TOKS];
#pragma unroll
    for (int t = 0; t < TOKS; t++) { best[t] = 3.4028235e38f; bidx[t] = 0; }

    for (int ch = 0; ch < K_CB / CHUNK; ch++) {
        __syncthreads();
        const float4* cp = reinterpret_cast<const float4*>(codebook + (size_t)ch * CHUNK * D_EMB);
        float4* scp = reinterpret_cast<float4*>(s_c);
#pragma unroll
        for (int i = 0; i < (CHUNK * D_EMB / 4) / TPB; i++)
            scp[tid + i * TPB] = cp[tid + i * TPB];
        if (tid < CHUNK) s_cn[tid] = g_cnorm[ch * CHUNK + tid];
        __syncthreads();

        for (int j = 0; j < CHUNK; j++) {
            const ulonglong2* csh = reinterpret_cast<const ulonglong2*>(s_c + j * D_EMB);
            u64 aXY[TOKS], aZW[TOKS];
#pragma unroll
            for (int t = 0; t < TOKS; t++) { aXY[t] = 0; aZW[t] = 0; }
#pragma unroll
            for (int i = 0; i < 16; i++) {
                ulonglong2 c2 = csh[i];   // LDS.128 broadcast, shared by 3 tokens
#pragma unroll
                for (int t = 0; t < TOKS; t++) {
                    ffma2(aXY[t], xs[t][i].x, c2.x);
                    ffma2(aZW[t], xs[t][i].y, c2.y);
                }
            }
            float cn = s_cn[j];
#pragma unroll
            for (int t = 0; t < TOKS; t++) {
                float2 uxy = unpack2(aXY[t]);
                float2 uzw = unpack2(aZW[t]);
                float dot = (uxy.x + uxy.y) + (uzw.x + uzw.y);
                float d = cn - 2.0f * dot;
                if (d < best[t]) { best[t] = d; bidx[t] = ch * CHUNK + j; }
            }
        }
    }

    // per-block count aggregation (guarded)
#pragma unroll
    for (int t = 0; t < TOKS; t++)
        if (gid0 + t * TPB < N_TOK) atomicAdd(&s_counts[bidx[t]], 1.0f);

    // gather + quantized store + loss + dw for valid tokens
    float lsum = 0.0f;
#pragma unroll
    for (int t = 0; t < TOKS; t++) {
        const int gid = gid0 + t * TPB;
        if (gid >= N_TOK) continue;
        const int bi = bidx[t];
        const float4* cch = reinterpret_cast<const float4*>(codebook + (size_t)bi * D_EMB);
        float4* qout = reinterpret_cast<float4*>(out + OFF_Q + (size_t)gid * D_EMB);
        float* dwrow = g_dw + (size_t)bi * D_EMB;
#pragma unroll
        for (int i = 0; i < 16; i++) {
            float4 c4 = cch[i];
            qout[i] = c4;
            float2 lo = unpack2(xs[t][i].x);
            float2 hi = unpack2(xs[t][i].y);
            float dx = c4.x - lo.x, dy = c4.y - lo.y;
            float dz = c4.z - hi.x, dwv = c4.w - hi.y;
            lsum += dx * dx + dy * dy + dz * dz + dwv * dwv;
            atomicAdd(dwrow + 4 * i + 0, lo.x);
            atomicAdd(dwrow + 4 * i + 1, lo.y);
            atomicAdd(dwrow + 4 * i + 2, hi.x);
            atomicAdd(dwrow + 4 * i + 3, hi.y);
        }
        out[OFF_IDX + gid] = (float)bi;
    }

    // block-reduce loss partial -> one global atomic per block
#pragma unroll
    for (int o = 16; o > 0; o >>= 1)
        lsum += __shfl_xor_sync(0xFFFFFFFFu, lsum, o);
    if ((tid & 31) == 0) s_red[tid >> 5] = lsum;
    __syncthreads();
    if (tid == 0) {
        float tt = 0.f;
#pragma unroll
        for (int w = 0; w < TPB / 32; w++) tt += s_red[w];
        atomicAdd(&g_loss, tt);
    }

    // flush block-local counts
    for (int i = tid; i < K_CB; i += TPB) {
        float v = s_counts[i];
        if (v != 0.0f) atomicAdd(&g_counts[i], v);
    }
}

// ---------------------------------------------------------------------------
// Stage 1 of finalize: new_cluster_size, n-reduction, loss. One block.
// ---------------------------------------------------------------------------
__global__ void __launch_bounds__(K_CB)
vq_ncs_kernel(const float* __restrict__ ema_cs, float* __restrict__ out) {
    __shared__ float s_n[K_CB];
    const int k = threadIdx.x;

    float ncs = DECAY * ema_cs[k] + (1.0f - DECAY) * g_counts[k];
    out[OFF_CS + k] = ncs;

    s_n[k] = ncs;
    __syncthreads();
#pragma unroll
    for (int s = K_CB / 2; s > 0; s >>= 1) {
        if (k < s) s_n[k] += s_n[k + s];
        __syncthreads();
    }
    if (k == 0) {
        g_n = s_n[0];
        out[OFF_LOSS] = COMMIT * g_loss / (float)((size_t)N_TOK * D_EMB);
    }
}

// ---------------------------------------------------------------------------
// Stage 2 of finalize: element-parallel EMA weight + codebook update.
// ---------------------------------------------------------------------------
__global__ void __launch_bounds__(256)
vq_update_kernel(const float* __restrict__ ema_w, float* __restrict__ out) {
    const int idx = blockIdx.x * 256 + threadIdx.x;   // 0 .. K*D-1
    const int k = idx >> 6;

    float ncs = out[OFF_CS + k];
    float n = g_n;
    float smoothed = (ncs + EPSV) / (n + (float)K_CB * EPSV) * n;

    float w = DECAY * ema_w[idx] + (1.0f - DECAY) * g_dw[idx];
    out[OFF_EW + idx] = w;
    out[OFF_CB + idx] = w / smoothed;
}

// ---------------------------------------------------------------------------
extern "C" void kernel_launch(void* const* d_in, const int* in_sizes, int n_in,
                              void* d_out, int out_size) {
    const float* inputs   = (const float*)d_in[0];
    const float* codebook = (const float*)d_in[1];
    const float* ema_cs   = (const float*)d_in[2];
    const float* ema_w    = (const float*)d_in[3];
    float* out = (float*)d_out;

    vq_zero_kernel<<<(K_CB * D_EMB + 255) / 256, 256>>>();
    vq_cnorm_kernel<<<(K_CB + 255) / 256, 256>>>(codebook);
    const int nblk = (N_TOK + TOKS * TPB - 1) / (TOKS * TPB);
    vq_assign_kernel<<<nblk, TPB>>>(inputs, codebook, out);
    vq_ncs_kernel<<<1, K_CB>>>(ema_cs, out);
    vq_update_kernel<<<(K_CB * D_EMB) / 256, 256>>>(ema_w, out);
}

// round 8
// speedup vs baseline: 1.7363x; 1.0931x over previous
#include <cuda_runtime.h>
#include <cstdint>

// Problem constants
#define N_TOK  262144
#define K_CB   1024
#define D_EMB  64
#define DECAY  0.99f
#define EPSV   1e-5f
#define COMMIT 0.25f

// Output layout (float32 blob, reference return order)
#define OFF_Q    0
#define OFF_LOSS 16777216
#define OFF_IDX  16777217
#define OFF_CB   17039361   // odd -> only 4-byte aligned
#define OFF_CS   17104897
#define OFF_EW   17105921   // odd -> only 4-byte aligned

// Scratch (device globals; no allocations allowed)
__device__ float    g_dw[K_CB * D_EMB];
__device__ float    g_counts[K_CB];
__device__ float    g_loss;
__device__ float    g_cnorm[K_CB];
__device__ float    g_n;
__device__ unsigned g_cbt[K_CB * D_EMB];   // codebook as tf32 bit patterns
__device__ unsigned g_xmax2;               // max ||x||^2 (float bits)
__device__ unsigned g_cmax2;               // max ||c||^2 (float bits)

// ---------------------------------------------------------------------------
__device__ __forceinline__ unsigned f2tf32(float f) {
    unsigned r; asm("cvt.rna.tf32.f32 %0, %1;" : "=r"(r) : "f"(f)); return r;
}

__device__ __forceinline__ void mma_tf32(float c[4], const unsigned a[4],
                                         unsigned b0, unsigned b1) {
    asm volatile(
        "mma.sync.aligned.m16n8k8.row.col.f32.tf32.tf32.f32 "
        "{%0,%1,%2,%3}, {%4,%5,%6,%7}, {%8,%9}, {%0,%1,%2,%3};"
        : "+f"(c[0]), "+f"(c[1]), "+f"(c[2]), "+f"(c[3])
        : "r"(a[0]), "r"(a[1]), "r"(a[2]), "r"(a[3]), "r"(b0), "r"(b1));
}

// Exact distance, bit-identical to the validated R2 chain ordering.
__device__ __forceinline__ float exact_d(const float4* x4, const float* crow, float cn) {
    const float4* c4 = reinterpret_cast<const float4*>(crow);
    float s0 = 0.f, s1 = 0.f, s2 = 0.f, s3 = 0.f;
#pragma unroll
    for (int i = 0; i < 16; i++) {
        float4 c = c4[i];
        s0 = fmaf(x4[i].x, c.x, s0);
        s1 = fmaf(x4[i].y, c.y, s1);
        s2 = fmaf(x4[i].z, c.z, s2);
        s3 = fmaf(x4[i].w, c.w, s3);
    }
    return cn - 2.0f * ((s0 + s1) + (s2 + s3));
}

// ---------------------------------------------------------------------------
// Zero scratch (graph replays require determinism)
// ---------------------------------------------------------------------------
__global__ void vq_zero_kernel() {
    int i = blockIdx.x * blockDim.x + threadIdx.x;
    if (i < K_CB * D_EMB) g_dw[i] = 0.0f;
    if (i < K_CB)         g_counts[i] = 0.0f;
    if (i == 0) { g_loss = 0.0f; g_xmax2 = 0u; g_cmax2 = 0u; }
}

// ---------------------------------------------------------------------------
// Prep codebook: exact cnorm (R2 chain), tf32 conversion, max ||c||^2.
// One block of 1024 threads.
// ---------------------------------------------------------------------------
__global__ void __launch_bounds__(K_CB)
vq_prep_cb_kernel(const float* __restrict__ codebook) {
    __shared__ float s_m[32];
    int k = threadIdx.x;
    const float4* c = reinterpret_cast<const float4*>(codebook + (size_t)k * D_EMB);
    float s0 = 0.f, s1 = 0.f, s2 = 0.f, s3 = 0.f;
#pragma unroll
    for (int i = 0; i < 16; i++) {
        float4 v = c[i];
        s0 += v.x * v.x; s1 += v.y * v.y;
        s2 += v.z * v.z; s3 += v.w * v.w;
    }
    float cn = (s0 + s1) + (s2 + s3);
    g_cnorm[k] = cn;
#pragma unroll
    for (int i = 0; i < D_EMB; i++)
        g_cbt[(size_t)k * D_EMB + i] = f2tf32(codebook[(size_t)k * D_EMB + i]);
    // block max of cn -> g_cmax2 (positive floats: unsigned-bit order == float order)
    float m = cn;
#pragma unroll
    for (int o = 16; o > 0; o >>= 1) m = fmaxf(m, __shfl_xor_sync(~0u, m, o));
    if ((k & 31) == 0) s_m[k >> 5] = m;
    __syncthreads();
    if (k == 0) {
        float t = s_m[0];
        for (int w = 1; w < 32; w++) t = fmaxf(t, s_m[w]);
        atomicMax(&g_cmax2, __float_as_uint(t));
    }
}

// ---------------------------------------------------------------------------
// Prep inputs: max ||x||^2 over all tokens. Token per thread.
// ---------------------------------------------------------------------------
__global__ void __launch_bounds__(256)
vq_prep_x_kernel(const float* __restrict__ inputs) {
    __shared__ float s_m[8];
    int t = blockIdx.x * 256 + threadIdx.x;
    const float4* x = reinterpret_cast<const float4*>(inputs + (size_t)t * D_EMB);
    float s = 0.f;
#pragma unroll
    for (int i = 0; i < 16; i++) {
        float4 v = x[i];
        s += v.x * v.x + v.y * v.y + v.z * v.z + v.w * v.w;
    }
#pragma unroll
    for (int o = 16; o > 0; o >>= 1) s = fmaxf(s, __shfl_xor_sync(~0u, s, o));
    if ((threadIdx.x & 31) == 0) s_m[threadIdx.x >> 5] = s;
    __syncthreads();
    if (threadIdx.x == 0) {
        float m = s_m[0];
        for (int w = 1; w < 8; w++) m = fmaxf(m, s_m[w]);
        atomicMax(&g_xmax2, __float_as_uint(m));
    }
}

// ---------------------------------------------------------------------------
// Screen kernel: tf32 mma.sync distance screen + exact rescore + epilogue.
// Block = 128 threads (4 warps), 128 tokens/block (32 per warp, two 16-row
// m16n8k8 tiles). Two sweeps over the codebook:
//   sweep 0: per-token min of approximate d~ (bit-deterministic)
//   sweep 1: collect all j with d~ <= min + 2W into per-token lists
// Then: exact rescore of candidates with the validated chain ordering
// (guaranteed to contain the exact argmin by the error bound W), fused with
// quantized/idx/loss/dw/counts epilogue.
// ---------------------------------------------------------------------------
#define SC_TPB   128
#define SC_TOKS  128
#define SC_CHUNK 128
#define CBS      68     // smem row stride (words) -> conflict-free B loads
#define MAXCAND  8

__global__ void __launch_bounds__(SC_TPB)
vq_screen_kernel(const float* __restrict__ inputs,
                 const float* __restrict__ codebook,
                 float* __restrict__ out) {
    __shared__ unsigned s_cb[SC_CHUNK * CBS];     // tf32 chunk
    __shared__ float    s_cn[SC_CHUNK];
    __shared__ int      s_cnt[SC_TOKS];
    __shared__ int      s_list[SC_TOKS * MAXCAND];
    __shared__ float    s_counts[K_CB];
    __shared__ float    s_red[SC_TPB / 32];

    const int tid  = threadIdx.x;
    const int warp = tid >> 5;
    const int lane = tid & 31;
    const int g    = lane >> 2;    // group id (row for A/C, code col for B)
    const int tq   = lane & 3;     // thread-in-group
    const int blkTok = blockIdx.x * SC_TOKS;
    const int tokBase = blkTok + warp * 32;

    // init smem
    if (tid < SC_TOKS) s_cnt[tid] = 0;
    for (int i = tid; i < K_CB; i += SC_TPB) s_counts[i] = 0.0f;

    // rigorous screen error bound (see derivation in round notes)
    const float W = 2.4e-3f * sqrtf(__uint_as_float(g_xmax2))
                            * sqrtf(__uint_as_float(g_cmax2)) + 1e-3f;
    const float WIN = 2.0f * W;

    // A fragments for both token tiles, all 8 k-steps (held in regs)
    unsigned afr[2][8][4];
#pragma unroll
    for (int T = 0; T < 2; T++) {
        const int r0 = tokBase + T * 16 + g;
        const int r1 = r0 + 8;
        const float* x0 = inputs + (size_t)r0 * D_EMB;
        const float* x1 = inputs + (size_t)r1 * D_EMB;
#pragma unroll
        for (int q = 0; q < 8; q++) {
            afr[T][q][0] = f2tf32(x0[q * 8 + tq]);
            afr[T][q][1] = f2tf32(x1[q * 8 + tq]);
            afr[T][q][2] = f2tf32(x0[q * 8 + tq + 4]);
            afr[T][q][3] = f2tf32(x1[q * 8 + tq + 4]);
        }
    }

    float rmin[2][2] = {{3.4e38f, 3.4e38f}, {3.4e38f, 3.4e38f}};
    float thr[2][2]  = {{0.f, 0.f}, {0.f, 0.f}};

    for (int sweep = 0; sweep < 2; sweep++) {
        for (int ch = 0; ch < K_CB / SC_CHUNK; ch++) {
            __syncthreads();
            // stage tf32 codebook chunk (stride CBS) + cnorms
            for (int i = tid; i < SC_CHUNK * D_EMB; i += SC_TPB) {
                int code = i >> 6, d = i & 63;
                s_cb[code * CBS + d] = g_cbt[(size_t)(ch * SC_CHUNK + code) * D_EMB + d];
            }
            if (tid < SC_CHUNK) s_cn[tid] = g_cnorm[ch * SC_CHUNK + tid];
            __syncthreads();

            for (int tile = 0; tile < SC_CHUNK / 8; tile++) {
                float c0[4] = {0.f, 0.f, 0.f, 0.f};
                float c1[4] = {0.f, 0.f, 0.f, 0.f};
                const unsigned* bb = s_cb + (tile * 8 + g) * CBS;
#pragma unroll
                for (int q = 0; q < 8; q++) {
                    unsigned b0 = bb[q * 8 + tq];
                    unsigned b1 = bb[q * 8 + tq + 4];
                    mma_tf32(c0, afr[0][q], b0, b1);
                    mma_tf32(c1, afr[1][q], b0, b1);
                }
                const int col0 = tile * 8 + tq * 2;
                const float cn0 = s_cn[col0], cn1 = s_cn[col0 + 1];
                // d~ values: rows g (c[0],c[1]) and g+8 (c[2],c[3])
                float dA0 = fmaf(-2.0f, c0[0], cn0), dA1 = fmaf(-2.0f, c0[1], cn1);
                float dA2 = fmaf(-2.0f, c0[2], cn0), dA3 = fmaf(-2.0f, c0[3], cn1);
                float dB0 = fmaf(-2.0f, c1[0], cn0), dB1 = fmaf(-2.0f, c1[1], cn1);
                float dB2 = fmaf(-2.0f, c1[2], cn0), dB3 = fmaf(-2.0f, c1[3], cn1);
                if (sweep == 0) {
                    rmin[0][0] = fminf(rmin[0][0], fminf(dA0, dA1));
                    rmin[0][1] = fminf(rmin[0][1], fminf(dA2, dA3));
                    rmin[1][0] = fminf(rmin[1][0], fminf(dB0, dB1));
                    rmin[1][1] = fminf(rmin[1][1], fminf(dB2, dB3));
                } else {
                    const int j0 = ch * SC_CHUNK + col0, j1 = j0 + 1;
                    const int s00 = warp * 32 + g;         // tile0 row g
                    const int s01 = s00 + 8;               // tile0 row g+8
                    const int s10 = s00 + 16;              // tile1 row g
                    const int s11 = s00 + 24;              // tile1 row g+8
                    if (dA0 <= thr[0][0]) { int p = atomicAdd(&s_cnt[s00], 1); if (p < MAXCAND) s_list[s00 * MAXCAND + p] = j0; }
                    if (dA1 <= thr[0][0]) { int p = atomicAdd(&s_cnt[s00], 1); if (p < MAXCAND) s_list[s00 * MAXCAND + p] = j1; }
                    if (dA2 <= thr[0][1]) { int p = atomicAdd(&s_cnt[s01], 1); if (p < MAXCAND) s_list[s01 * MAXCAND + p] = j0; }
                    if (dA3 <= thr[0][1]) { int p = atomicAdd(&s_cnt[s01], 1); if (p < MAXCAND) s_list[s01 * MAXCAND + p] = j1; }
                    if (dB0 <= thr[1][0]) { int p = atomicAdd(&s_cnt[s10], 1); if (p < MAXCAND) s_list[s10 * MAXCAND + p] = j0; }
                    if (dB1 <= thr[1][0]) { int p = atomicAdd(&s_cnt[s10], 1); if (p < MAXCAND) s_list[s10 * MAXCAND + p] = j1; }
                    if (dB2 <= thr[1][1]) { int p = atomicAdd(&s_cnt[s11], 1); if (p < MAXCAND) s_list[s11 * MAXCAND + p] = j0; }
                    if (dB3 <= thr[1][1]) { int p = atomicAdd(&s_cnt[s11], 1); if (p < MAXCAND) s_list[s11 * MAXCAND + p] = j1; }
                }
            }
        }
        if (sweep == 0) {
            // quad-reduce lane mins (cols) -> per-row global min -> thresholds
#pragma unroll
            for (int T = 0; T < 2; T++)
#pragma unroll
                for (int r = 0; r < 2; r++) {
                    float v = rmin[T][r];
                    v = fminf(v, __shfl_xor_sync(~0u, v, 1));
                    v = fminf(v, __shfl_xor_sync(~0u, v, 2));
                    thr[T][r] = v + WIN;
                }
        }
    }
    __syncthreads();

    // ---- exact rescore + epilogue: thread tid owns block-token slot tid ----
    const int gid = blkTok + tid;
    float4 x4[16];
    const float4* xp = reinterpret_cast<const float4*>(inputs + (size_t)gid * D_EMB);
#pragma unroll
    for (int i = 0; i < 16; i++) x4[i] = xp[i];

    float best = 3.4028235e38f;
    int   bi = 0;
    const int cnt = s_cnt[tid];
    if (cnt <= MAXCAND) {
        for (int c = 0; c < cnt; c++) {
            int j = s_list[tid * MAXCAND + c];
            float d = exact_d(x4, codebook + (size_t)j * D_EMB, g_cnorm[j]);
            if (d < best || (d == best && j < bi)) { best = d; bi = j; }
        }
    } else {
        // overflow fallback: exact full scan, ascending j, strict <
        for (int j = 0; j < K_CB; j++) {
            float d = exact_d(x4, codebook + (size_t)j * D_EMB, g_cnorm[j]);
            if (d < best) { best = d; bi = j; }
        }
    }

    atomicAdd(&s_counts[bi], 1.0f);

    const float4* cch = reinterpret_cast<const float4*>(codebook + (size_t)bi * D_EMB);
    float4* qout = reinterpret_cast<float4*>(out + OFF_Q + (size_t)gid * D_EMB);
    float* dwrow = g_dw + (size_t)bi * D_EMB;
    float lsum = 0.0f;
#pragma unroll
    for (int i = 0; i < 16; i++) {
        float4 c4 = cch[i];
        qout[i] = c4;
        float dx = c4.x - x4[i].x, dy = c4.y - x4[i].y;
        float dz = c4.z - x4[i].z, dwv = c4.w - x4[i].w;
        lsum += dx * dx + dy * dy + dz * dz + dwv * dwv;
        atomicAdd(dwrow + 4 * i + 0, x4[i].x);
        atomicAdd(dwrow + 4 * i + 1, x4[i].y);
        atomicAdd(dwrow + 4 * i + 2, x4[i].z);
        atomicAdd(dwrow + 4 * i + 3, x4[i].w);
    }
    out[OFF_IDX + gid] = (float)bi;

    // block loss reduction
#pragma unroll
    for (int o = 16; o > 0; o >>= 1)
        lsum += __shfl_xor_sync(~0u, lsum, o);
    if (lane == 0) s_red[warp] = lsum;
    __syncthreads();
    if (tid == 0) {
        float t = 0.f;
#pragma unroll
        for (int w = 0; w < SC_TPB / 32; w++) t += s_red[w];
        atomicAdd(&g_loss, t);
    }

    // flush block-local counts
    for (int i = tid; i < K_CB; i += SC_TPB) {
        float v = s_counts[i];
        if (v != 0.0f) atomicAdd(&g_counts[i], v);
    }
}

// ---------------------------------------------------------------------------
// Finalize stage 1: new_cluster_size, n-reduction, loss. One block.
// ---------------------------------------------------------------------------
__global__ void __launch_bounds__(K_CB)
vq_ncs_kernel(const float* __restrict__ ema_cs, float* __restrict__ out) {
    __shared__ float s_n[K_CB];
    const int k = threadIdx.x;

    float ncs = DECAY * ema_cs[k] + (1.0f - DECAY) * g_counts[k];
    out[OFF_CS + k] = ncs;

    s_n[k] = ncs;
    __syncthreads();
#pragma unroll
    for (int s = K_CB / 2; s > 0; s >>= 1) {
        if (k < s) s_n[k] += s_n[k + s];
        __syncthreads();
    }
    if (k == 0) {
        g_n = s_n[0];
        out[OFF_LOSS] = COMMIT * g_loss / (float)((size_t)N_TOK * D_EMB);
    }
}

// ---------------------------------------------------------------------------
// Finalize stage 2: element-parallel EMA weight + codebook update.
// ---------------------------------------------------------------------------
__global__ void __launch_bounds__(256)
vq_update_kernel(const float* __restrict__ ema_w, float* __restrict__ out) {
    const int idx = blockIdx.x * 256 + threadIdx.x;   // 0 .. K*D-1
    const int k = idx >> 6;

    float ncs = out[OFF_CS + k];
    float n = g_n;
    float smoothed = (ncs + EPSV) / (n + (float)K_CB * EPSV) * n;

    float w = DECAY * ema_w[idx] + (1.0f - DECAY) * g_dw[idx];
    out[OFF_EW + idx] = w;
    out[OFF_CB + idx] = w / smoothed;
}

// ---------------------------------------------------------------------------
extern "C" void kernel_launch(void* const* d_in, const int* in_sizes, int n_in,
                              void* d_out, int out_size) {
    const float* inputs   = (const float*)d_in[0];
    const float* codebook = (const float*)d_in[1];
    const float* ema_cs   = (const float*)d_in[2];
    const float* ema_w    = (const float*)d_in[3];
    float* out = (float*)d_out;

    vq_zero_kernel<<<(K_CB * D_EMB + 255) / 256, 256>>>();
    vq_prep_cb_kernel<<<1, K_CB>>>(codebook);
    vq_prep_x_kernel<<<N_TOK / 256, 256>>>(inputs);
    vq_screen_kernel<<<N_TOK / SC_TOKS, SC_TPB>>>(inputs, codebook, out);
    vq_ncs_kernel<<<1, K_CB>>>(ema_cs, out);
    vq_update_kernel<<<(K_CB * D_EMB) / 256, 256>>>(ema_w, out);
}